// round 2
// baseline (speedup 1.0000x reference)
#include <cuda_runtime.h>
#include <cuda_bf16.h>

#define NN 50000
#define EE 800000
#define GG 64
#define HH 64

// ---------------- scratch (device globals; no allocation allowed) ----------
__device__ __align__(16) float g_deg_in[NN];
__device__ __align__(16) float g_deg_out[NN];
__device__ __align__(16) float g_norm_src[NN];
__device__ __align__(16) float g_norm_dst[NN];
__device__ __align__(16) float g_hsrc[NN * HH];   // layer inputs (pre-scaled by norm_src)
__device__ __align__(16) float g_agg[NN * HH];    // scatter-add target
__device__ __align__(16) float g_gsum[GG * HH];   // graph pooling sums
__device__ __align__(16) float g_gcnt[GG];

// ---------------- helpers ---------------------------------------------------
__device__ __forceinline__ void red4(float* p, float4 v) {
    asm volatile("red.global.add.v4.f32 [%0], {%1, %2, %3, %4};"
                 :: "l"(p), "f"(v.x), "f"(v.y), "f"(v.z), "f"(v.w) : "memory");
}

// ---------------- kernels ---------------------------------------------------

// zero degrees + pooling buffers
__global__ void init_kernel() {
    int i = blockIdx.x * blockDim.x + threadIdx.x;
    if (i < NN) { g_deg_in[i] = 0.f; g_deg_out[i] = 0.f; }
    if (i < GG * HH) g_gsum[i] = 0.f;
    if (i < GG) g_gcnt[i] = 0.f;
}

// zero n4 float4's of g_agg
__global__ void zero_agg_kernel(int n4) {
    int i = blockIdx.x * blockDim.x + threadIdx.x;
    if (i < n4) reinterpret_cast<float4*>(g_agg)[i] = make_float4(0.f, 0.f, 0.f, 0.f);
}

__global__ void deg_kernel(const int* __restrict__ src, const int* __restrict__ dst) {
    int e = blockIdx.x * blockDim.x + threadIdx.x;
    if (e >= EE) return;
    atomicAdd(&g_deg_in[dst[e]], 1.f);
    atomicAdd(&g_deg_out[src[e]], 1.f);
}

// build input features (pre-scaled by norm_src), norms, graph counts
__global__ void feats_kernel(const int* __restrict__ graph_ids) {
    int n = blockIdx.x * blockDim.x + threadIdx.x;
    if (n >= NN) return;
    float di = g_deg_in[n];
    float dout = g_deg_out[n];
    float h1 = di;
    float h2 = (di - 3.f > 0.f) ? 1.f : 0.f;
    float h3 = 3.f / di;
    float h4 = (di - 4.f > 0.f) ? 1.f : 0.f;
    float ns = rsqrtf(fmaxf(dout, 1.f));
    float nd = rsqrtf(fmaxf(di, 1.f));
    g_norm_src[n] = ns;
    g_norm_dst[n] = nd;
    reinterpret_cast<float4*>(g_hsrc)[n] =
        make_float4(h1 * ns, h2 * ns, h3 * ns, h4 * ns);
    atomicAdd(&g_gcnt[graph_ids[n]], 1.f);
}

// layer-1 message passing: 4-wide features, one thread per edge
__global__ void edge1_kernel(const int* __restrict__ src, const int* __restrict__ dst) {
    int e = blockIdx.x * blockDim.x + threadIdx.x;
    if (e >= EE) return;
    int s = src[e], d = dst[e];
    float4 v = reinterpret_cast<const float4*>(g_hsrc)[s];
    red4(g_agg + d * 4, v);
}

// layers 2..4 message passing: 64-wide features, 16 threads (4 float4) per edge
__global__ void edgeH_kernel(const int* __restrict__ src, const int* __restrict__ dst) {
    int t = blockIdx.x * blockDim.x + threadIdx.x;
    if (t >= EE * 16) return;
    int e = t >> 4;
    int c = t & 15;
    int s = src[e], d = dst[e];
    float4 v = reinterpret_cast<const float4*>(g_hsrc)[s * 16 + c];
    red4(g_agg + d * HH + c * 4, v);
}

// layer-1 node update: h = relu(agg*nd @ W1(4x64) + b1), out pre-scaled by ns
__global__ void node_first_kernel(const float* __restrict__ W1, const float* __restrict__ b1) {
    int t = blockIdx.x * blockDim.x + threadIdx.x;
    if (t >= NN * HH) return;
    int n = t >> 6;
    int o = t & 63;
    float nd = g_norm_dst[n];
    float ns = g_norm_src[n];
    float4 x = reinterpret_cast<const float4*>(g_agg)[n];
    float acc = b1[o];
    acc = fmaf(x.x * nd, W1[0 * HH + o], acc);
    acc = fmaf(x.y * nd, W1[1 * HH + o], acc);
    acc = fmaf(x.z * nd, W1[2 * HH + o], acc);
    acc = fmaf(x.w * nd, W1[3 * HH + o], acc);
    acc = fmaxf(acc, 0.f) * ns;
    g_hsrc[t] = acc;
}

// layers 2..4 node update: 16 nodes per block iter, 16 threads x float4 per node.
// LAST=false: write relu(.)*norm_src into g_hsrc.
// LAST=true : pool relu(.) into g_gsum via red.v4 (graph_ids sorted -> low contention).
template <bool LAST>
__global__ void node_kernel(const float* __restrict__ W, const float* __restrict__ b,
                            const int* __restrict__ graph_ids) {
    __shared__ float Ws[HH * HH];
    __shared__ float bs[HH];
    __shared__ float xs[16 * 68];   // stride 68 to dodge bank conflicts

    int tid = threadIdx.x;
    float4* Ws4 = reinterpret_cast<float4*>(Ws);
    const float4* Wg4 = reinterpret_cast<const float4*>(W);
    for (int i = tid; i < HH * HH / 4; i += 256) Ws4[i] = Wg4[i];
    if (tid < HH) bs[tid] = b[tid];
    __syncthreads();

    int slot = tid >> 4;
    int o4 = tid & 15;

    for (int base = blockIdx.x * 16; base < NN; base += gridDim.x * 16) {
        int n = base + slot;
        if (n < NN) {
            float nd = g_norm_dst[n];
            float4 xv = reinterpret_cast<const float4*>(g_agg)[n * 16 + o4];
            xv.x *= nd; xv.y *= nd; xv.z *= nd; xv.w *= nd;
            reinterpret_cast<float4*>(xs + slot * 68)[o4] = xv;
        }
        __syncthreads();
        if (n < NN) {
            float4 acc = reinterpret_cast<float4*>(bs)[o4];
            const float* xrow = xs + slot * 68;
#pragma unroll
            for (int k = 0; k < HH; k++) {
                float xk = xrow[k];
                float4 w = Ws4[k * 16 + o4];
                acc.x = fmaf(xk, w.x, acc.x);
                acc.y = fmaf(xk, w.y, acc.y);
                acc.z = fmaf(xk, w.z, acc.z);
                acc.w = fmaf(xk, w.w, acc.w);
            }
            acc.x = fmaxf(acc.x, 0.f);
            acc.y = fmaxf(acc.y, 0.f);
            acc.z = fmaxf(acc.z, 0.f);
            acc.w = fmaxf(acc.w, 0.f);
            if (!LAST) {
                float ns = g_norm_src[n];
                acc.x *= ns; acc.y *= ns; acc.z *= ns; acc.w *= ns;
                reinterpret_cast<float4*>(g_hsrc)[n * 16 + o4] = acc;
            } else {
                int g = graph_ids[n];
                red4(&g_gsum[g * HH + o4 * 4], acc);
            }
        }
        __syncthreads();
    }
}

// final head: per-graph mean, dot with Wout, + bout, sigmoid
__global__ void out_kernel(const float* __restrict__ Wout, const float* __restrict__ bout,
                           float* __restrict__ out) {
    __shared__ float s[HH];
    int g = blockIdx.x;
    int t = threadIdx.x;
    float inv = 1.f / g_gcnt[g];
    float v = g_gsum[g * HH + t] * inv * Wout[t];
    s[t] = v;
    __syncthreads();
    if (t < 32) {
        float x = s[t] + s[t + 32];
#pragma unroll
        for (int off = 16; off > 0; off >>= 1)
            x += __shfl_xor_sync(0xFFFFFFFF, x, off);
        if (t == 0) out[g] = 1.f / (1.f + expf(-(x + bout[0])));
    }
}

// ---------------- launch -----------------------------------------------------
extern "C" void kernel_launch(void* const* d_in, const int* in_sizes, int n_in,
                              void* d_out, int out_size) {
    const int*   src  = (const int*)d_in[0];
    const int*   dst  = (const int*)d_in[1];
    const int*   gids = (const int*)d_in[2];
    const float* W1   = (const float*)d_in[3];
    const float* b1   = (const float*)d_in[4];
    const float* W2   = (const float*)d_in[5];
    const float* b2   = (const float*)d_in[6];
    const float* W3   = (const float*)d_in[7];
    const float* b3   = (const float*)d_in[8];
    const float* W4   = (const float*)d_in[9];
    const float* b4   = (const float*)d_in[10];
    const float* Wout = (const float*)d_in[11];
    const float* bout = (const float*)d_in[12];
    float* out = (float*)d_out;

    const int T = 256;
    const int gridN  = (NN + T - 1) / T;
    const int gridE  = (EE + T - 1) / T;
    const int gridE16 = (EE * 16 + T - 1) / T;
    const int gridNH = (NN * HH + T - 1) / T;
    const int gridNode = 592;   // ~4 blocks/SM, persistent loop over nodes

    init_kernel<<<gridN, T>>>();
    deg_kernel<<<gridE, T>>>(src, dst);
    feats_kernel<<<gridN, T>>>(gids);

    // layer 1 (4-wide)
    zero_agg_kernel<<<(NN + T - 1) / T, T>>>(NN);              // NN float4's = N*4 floats
    edge1_kernel<<<gridE, T>>>(src, dst);
    node_first_kernel<<<gridNH, T>>>(W1, b1);

    // layer 2
    zero_agg_kernel<<<(NN * 16 + T - 1) / T, T>>>(NN * 16);
    edgeH_kernel<<<gridE16, T>>>(src, dst);
    node_kernel<false><<<gridNode, T>>>(W2, b2, gids);

    // layer 3
    zero_agg_kernel<<<(NN * 16 + T - 1) / T, T>>>(NN * 16);
    edgeH_kernel<<<gridE16, T>>>(src, dst);
    node_kernel<false><<<gridNode, T>>>(W3, b3, gids);

    // layer 4 (+ fused pooling)
    zero_agg_kernel<<<(NN * 16 + T - 1) / T, T>>>(NN * 16);
    edgeH_kernel<<<gridE16, T>>>(src, dst);
    node_kernel<true><<<gridNode, T>>>(W4, b4, gids);

    out_kernel<<<GG, HH>>>(Wout, bout, out);
}

// round 3
// speedup vs baseline: 1.2859x; 1.2859x over previous
#include <cuda_runtime.h>
#include <cuda_bf16.h>

#define NN 50000
#define EE 800000
#define GG 64
#define HH 64
#define NB ((NN + 255) / 256)   // 196 scan blocks

// ---------------- scratch (device globals; no allocation allowed) ----------
__device__ __align__(16) int   g_degin_i[NN];
__device__ __align__(16) int   g_degout_i[NN];
__device__ __align__(16) int   g_rowptr[NN + 1];
__device__ __align__(16) int   g_cursor[NN];
__device__ __align__(16) int   g_blocksum[NB];
__device__ __align__(16) int   g_csr_src[EE];
__device__ __align__(16) float g_norm_src[NN];
__device__ __align__(16) float g_norm_dst[NN];
__device__ __align__(16) float g_hsrc[NN * HH];   // layer inputs (pre-scaled by norm_src)
__device__ __align__(16) float g_agg[NN * HH];    // aggregation output
__device__ __align__(16) float g_gsum[GG * HH];   // graph pooling sums
__device__ __align__(16) float g_gcnt[GG];

// ---------------- helpers ---------------------------------------------------
__device__ __forceinline__ void red4(float* p, float4 v) {
    asm volatile("red.global.add.v4.f32 [%0], {%1, %2, %3, %4};"
                 :: "l"(p), "f"(v.x), "f"(v.y), "f"(v.z), "f"(v.w) : "memory");
}

// ---------------- CSR build --------------------------------------------------
__global__ void init_kernel() {
    int i = blockIdx.x * blockDim.x + threadIdx.x;
    if (i < NN) { g_degin_i[i] = 0; g_degout_i[i] = 0; }
    if (i < GG * HH) g_gsum[i] = 0.f;
    if (i < GG) g_gcnt[i] = 0.f;
}

__global__ void deg_kernel(const int* __restrict__ src, const int* __restrict__ dst) {
    int e = blockIdx.x * blockDim.x + threadIdx.x;
    if (e >= EE) return;
    atomicAdd(&g_degin_i[dst[e]], 1);
    atomicAdd(&g_degout_i[src[e]], 1);
}

// per-block exclusive scan of in-degrees; partial rowptr + block totals
__global__ void scanA_kernel() {
    __shared__ int s[256];
    int t = threadIdx.x;
    int n = blockIdx.x * 256 + t;
    int v = (n < NN) ? g_degin_i[n] : 0;
    s[t] = v;
    __syncthreads();
#pragma unroll
    for (int off = 1; off < 256; off <<= 1) {
        int add = (t >= off) ? s[t - off] : 0;
        __syncthreads();
        s[t] += add;
        __syncthreads();
    }
    if (n < NN) g_rowptr[n] = s[t] - v;          // exclusive within block
    if (t == 255) g_blocksum[blockIdx.x] = s[255];
}

// tiny sequential scan of block sums
__global__ void scanB_kernel() {
    if (threadIdx.x == 0) {
        int acc = 0;
        for (int b = 0; b < NB; b++) {
            int v = g_blocksum[b];
            g_blocksum[b] = acc;
            acc += v;
        }
        g_rowptr[NN] = EE;
    }
}

// add block offsets; init cursors
__global__ void scanC_kernel() {
    int n = blockIdx.x * blockDim.x + threadIdx.x;
    if (n >= NN) return;
    int r = g_rowptr[n] + g_blocksum[blockIdx.x * 256 >= 0 ? blockIdx.x : 0];
    r = g_rowptr[n] + g_blocksum[n >> 8];
    g_rowptr[n] = r;
    g_cursor[n] = r;
}

__global__ void scatter_kernel(const int* __restrict__ src, const int* __restrict__ dst) {
    int e = blockIdx.x * blockDim.x + threadIdx.x;
    if (e >= EE) return;
    int d = dst[e];
    int pos = atomicAdd(&g_cursor[d], 1);
    g_csr_src[pos] = src[e];
}

// build input features (pre-scaled by norm_src), norms, graph counts
__global__ void feats_kernel(const int* __restrict__ graph_ids) {
    int n = blockIdx.x * blockDim.x + threadIdx.x;
    if (n >= NN) return;
    float di = (float)g_degin_i[n];
    float dout = (float)g_degout_i[n];
    float h1 = di;
    float h2 = (di - 3.f > 0.f) ? 1.f : 0.f;
    float h3 = 3.f / di;
    float h4 = (di - 4.f > 0.f) ? 1.f : 0.f;
    float ns = rsqrtf(fmaxf(dout, 1.f));
    float nd = rsqrtf(fmaxf(di, 1.f));
    g_norm_src[n] = ns;
    g_norm_dst[n] = nd;
    reinterpret_cast<float4*>(g_hsrc)[n] =
        make_float4(h1 * ns, h2 * ns, h3 * ns, h4 * ns);
    atomicAdd(&g_gcnt[graph_ids[n]], 1.f);
}

// ---------------- aggregation (gather, no atomics) ---------------------------

// layer-1: 4-wide features, one thread per node
__global__ void agg1_kernel() {
    int n = blockIdx.x * blockDim.x + threadIdx.x;
    if (n >= NN) return;
    int e0 = g_rowptr[n], e1 = g_rowptr[n + 1];
    const float4* h4 = reinterpret_cast<const float4*>(g_hsrc);
    float4 acc = make_float4(0.f, 0.f, 0.f, 0.f);
    for (int e = e0; e < e1; e++) {
        float4 v = h4[g_csr_src[e]];
        acc.x += v.x; acc.y += v.y; acc.z += v.z; acc.w += v.w;
    }
    reinterpret_cast<float4*>(g_agg)[n] = acc;
}

// layers 2..4: 64-wide features, 16 threads (one float4 lane) per node
__global__ void aggH_kernel() {
    long long t = (long long)blockIdx.x * blockDim.x + threadIdx.x;
    int n = (int)(t >> 4);
    int c = (int)(t & 15);
    if (n >= NN) return;
    int e0 = g_rowptr[n], e1 = g_rowptr[n + 1];
    const float4* h4 = reinterpret_cast<const float4*>(g_hsrc);
    float4 acc = make_float4(0.f, 0.f, 0.f, 0.f);
    int e = e0;
    // unroll-by-2 for memory-level parallelism
    for (; e + 1 < e1; e += 2) {
        int s0 = g_csr_src[e];
        int s1 = g_csr_src[e + 1];
        float4 v0 = h4[s0 * 16 + c];
        float4 v1 = h4[s1 * 16 + c];
        acc.x += v0.x; acc.y += v0.y; acc.z += v0.z; acc.w += v0.w;
        acc.x += v1.x; acc.y += v1.y; acc.z += v1.z; acc.w += v1.w;
    }
    if (e < e1) {
        float4 v = h4[g_csr_src[e] * 16 + c];
        acc.x += v.x; acc.y += v.y; acc.z += v.z; acc.w += v.w;
    }
    reinterpret_cast<float4*>(g_agg)[n * 16 + c] = acc;
}

// ---------------- node updates ------------------------------------------------

// layer-1 node update: h = relu(agg*nd @ W1(4x64) + b1), out pre-scaled by ns
__global__ void node_first_kernel(const float* __restrict__ W1, const float* __restrict__ b1) {
    int t = blockIdx.x * blockDim.x + threadIdx.x;
    if (t >= NN * HH) return;
    int n = t >> 6;
    int o = t & 63;
    float nd = g_norm_dst[n];
    float ns = g_norm_src[n];
    float4 x = reinterpret_cast<const float4*>(g_agg)[n];
    float acc = b1[o];
    acc = fmaf(x.x * nd, W1[0 * HH + o], acc);
    acc = fmaf(x.y * nd, W1[1 * HH + o], acc);
    acc = fmaf(x.z * nd, W1[2 * HH + o], acc);
    acc = fmaf(x.w * nd, W1[3 * HH + o], acc);
    acc = fmaxf(acc, 0.f) * ns;
    g_hsrc[t] = acc;
}

// layers 2..4 node update: 16 nodes per block iter, 16 threads x float4 per node.
template <bool LAST>
__global__ void node_kernel(const float* __restrict__ W, const float* __restrict__ b,
                            const int* __restrict__ graph_ids) {
    __shared__ float Ws[HH * HH];
    __shared__ float bs[HH];
    __shared__ float xs[16 * 68];

    int tid = threadIdx.x;
    float4* Ws4 = reinterpret_cast<float4*>(Ws);
    const float4* Wg4 = reinterpret_cast<const float4*>(W);
    for (int i = tid; i < HH * HH / 4; i += 256) Ws4[i] = Wg4[i];
    if (tid < HH) bs[tid] = b[tid];
    __syncthreads();

    int slot = tid >> 4;
    int o4 = tid & 15;

    for (int base = blockIdx.x * 16; base < NN; base += gridDim.x * 16) {
        int n = base + slot;
        if (n < NN) {
            float nd = g_norm_dst[n];
            float4 xv = reinterpret_cast<const float4*>(g_agg)[n * 16 + o4];
            xv.x *= nd; xv.y *= nd; xv.z *= nd; xv.w *= nd;
            reinterpret_cast<float4*>(xs + slot * 68)[o4] = xv;
        }
        __syncthreads();
        if (n < NN) {
            float4 acc = reinterpret_cast<float4*>(bs)[o4];
            const float* xrow = xs + slot * 68;
#pragma unroll
            for (int k = 0; k < HH; k++) {
                float xk = xrow[k];
                float4 w = Ws4[k * 16 + o4];
                acc.x = fmaf(xk, w.x, acc.x);
                acc.y = fmaf(xk, w.y, acc.y);
                acc.z = fmaf(xk, w.z, acc.z);
                acc.w = fmaf(xk, w.w, acc.w);
            }
            acc.x = fmaxf(acc.x, 0.f);
            acc.y = fmaxf(acc.y, 0.f);
            acc.z = fmaxf(acc.z, 0.f);
            acc.w = fmaxf(acc.w, 0.f);
            if (!LAST) {
                float ns = g_norm_src[n];
                acc.x *= ns; acc.y *= ns; acc.z *= ns; acc.w *= ns;
                reinterpret_cast<float4*>(g_hsrc)[n * 16 + o4] = acc;
            } else {
                int g = graph_ids[n];
                red4(&g_gsum[g * HH + o4 * 4], acc);
            }
        }
        __syncthreads();
    }
}

// final head: per-graph mean, dot with Wout, + bout, sigmoid
__global__ void out_kernel(const float* __restrict__ Wout, const float* __restrict__ bout,
                           float* __restrict__ out) {
    __shared__ float s[HH];
    int g = blockIdx.x;
    int t = threadIdx.x;
    float inv = 1.f / g_gcnt[g];
    float v = g_gsum[g * HH + t] * inv * Wout[t];
    s[t] = v;
    __syncthreads();
    if (t < 32) {
        float x = s[t] + s[t + 32];
#pragma unroll
        for (int off = 16; off > 0; off >>= 1)
            x += __shfl_xor_sync(0xFFFFFFFF, x, off);
        if (t == 0) out[g] = 1.f / (1.f + expf(-(x + bout[0])));
    }
}

// ---------------- launch -----------------------------------------------------
extern "C" void kernel_launch(void* const* d_in, const int* in_sizes, int n_in,
                              void* d_out, int out_size) {
    const int*   src  = (const int*)d_in[0];
    const int*   dst  = (const int*)d_in[1];
    const int*   gids = (const int*)d_in[2];
    const float* W1   = (const float*)d_in[3];
    const float* b1   = (const float*)d_in[4];
    const float* W2   = (const float*)d_in[5];
    const float* b2   = (const float*)d_in[6];
    const float* W3   = (const float*)d_in[7];
    const float* b3   = (const float*)d_in[8];
    const float* W4   = (const float*)d_in[9];
    const float* b4   = (const float*)d_in[10];
    const float* Wout = (const float*)d_in[11];
    const float* bout = (const float*)d_in[12];
    float* out = (float*)d_out;

    const int T = 256;
    const int gridN   = (NN + T - 1) / T;
    const int gridE   = (EE + T - 1) / T;
    const int gridN16 = (NN * 16 + T - 1) / T;
    const int gridNH  = (NN * HH + T - 1) / T;
    const int gridNode = 592;

    // CSR build (once; reused for all 4 layers)
    init_kernel<<<gridN, T>>>();
    deg_kernel<<<gridE, T>>>(src, dst);
    scanA_kernel<<<NB, 256>>>();
    scanB_kernel<<<1, 32>>>();
    scanC_kernel<<<gridN, T>>>();
    scatter_kernel<<<gridE, T>>>(src, dst);
    feats_kernel<<<gridN, T>>>(gids);

    // layer 1 (4-wide)
    agg1_kernel<<<gridN, T>>>();
    node_first_kernel<<<gridNH, T>>>(W1, b1);

    // layer 2
    aggH_kernel<<<gridN16, T>>>();
    node_kernel<false><<<gridNode, T>>>(W2, b2, gids);

    // layer 3
    aggH_kernel<<<gridN16, T>>>();
    node_kernel<false><<<gridNode, T>>>(W3, b3, gids);

    // layer 4 (+ fused pooling)
    aggH_kernel<<<gridN16, T>>>();
    node_kernel<true><<<gridNode, T>>>(W4, b4, gids);

    out_kernel<<<GG, HH>>>(Wout, bout, out);
}

// round 5
// speedup vs baseline: 1.3888x; 1.0800x over previous
#include <cuda_runtime.h>
#include <cuda_bf16.h>

#define NN 50000
#define EE 800000
#define GG 64
#define HH 64
#define NB ((NN + 255) / 256)   // 196 scan blocks

// ---------------- scratch (device globals; no allocation allowed) ----------
__device__ __align__(16) int   g_degin_i[NN];
__device__ __align__(16) int   g_degout_i[NN];
__device__ __align__(16) int   g_rowptr[NN + 1];
__device__ __align__(16) int   g_cursor[NN];
__device__ __align__(16) int   g_blocksum[NB];
__device__ __align__(16) int   g_csr_src[EE];
__device__ __align__(16) float g_norm_src[NN];
__device__ __align__(16) float g_norm_dst[NN];
__device__ __align__(16) float g_hA[NN * HH];     // feature ping buffer
__device__ __align__(16) float g_hB[NN * HH];     // feature pong buffer
__device__ __align__(16) float g_agg1[NN * 4];    // layer-1 aggregation (4-wide only)
__device__ __align__(16) float g_gsum[GG * HH];   // graph pooling sums
__device__ __align__(16) float g_gcnt[GG];

// ---------------- helpers ---------------------------------------------------
__device__ __forceinline__ void red4(float* p, float4 v) {
    asm volatile("red.global.add.v4.f32 [%0], {%1, %2, %3, %4};"
                 :: "l"(p), "f"(v.x), "f"(v.y), "f"(v.z), "f"(v.w) : "memory");
}

// ---------------- CSR build --------------------------------------------------
__global__ void init_kernel() {
    int i = blockIdx.x * blockDim.x + threadIdx.x;
    if (i < NN) { g_degin_i[i] = 0; g_degout_i[i] = 0; }
    if (i < GG * HH) g_gsum[i] = 0.f;
    if (i < GG) g_gcnt[i] = 0.f;
}

__global__ void deg_kernel(const int* __restrict__ src, const int* __restrict__ dst) {
    int e = blockIdx.x * blockDim.x + threadIdx.x;
    if (e >= EE) return;
    atomicAdd(&g_degin_i[dst[e]], 1);
    atomicAdd(&g_degout_i[src[e]], 1);
}

// per-block exclusive scan of in-degrees; partial rowptr + block totals
__global__ void scanA_kernel() {
    __shared__ int s[256];
    int t = threadIdx.x;
    int n = blockIdx.x * 256 + t;
    int v = (n < NN) ? g_degin_i[n] : 0;
    s[t] = v;
    __syncthreads();
#pragma unroll
    for (int off = 1; off < 256; off <<= 1) {
        int add = (t >= off) ? s[t - off] : 0;
        __syncthreads();
        s[t] += add;
        __syncthreads();
    }
    if (n < NN) g_rowptr[n] = s[t] - v;          // exclusive within block
    if (t == 255) g_blocksum[blockIdx.x] = s[255];
}

// parallel exclusive scan of the 196 block sums (one 256-thread block)
__global__ void scanB_kernel() {
    __shared__ int s[256];
    int t = threadIdx.x;
    int v = (t < NB) ? g_blocksum[t] : 0;
    s[t] = v;
    __syncthreads();
#pragma unroll
    for (int off = 1; off < 256; off <<= 1) {
        int add = (t >= off) ? s[t - off] : 0;
        __syncthreads();
        s[t] += add;
        __syncthreads();
    }
    if (t < NB) g_blocksum[t] = s[t] - v;        // exclusive
    if (t == 0) g_rowptr[NN] = EE;
}

// add block offsets, init cursors, AND build features/norms (fused)
__global__ void scanC_feats_kernel(const int* __restrict__ graph_ids) {
    int n = blockIdx.x * blockDim.x + threadIdx.x;
    if (n >= NN) return;
    int r = g_rowptr[n] + g_blocksum[n >> 8];
    g_rowptr[n] = r;
    g_cursor[n] = r;

    float di = (float)g_degin_i[n];
    float dout = (float)g_degout_i[n];
    float h1 = di;
    float h2 = (di - 3.f > 0.f) ? 1.f : 0.f;
    float h3 = 3.f / di;
    float h4 = (di - 4.f > 0.f) ? 1.f : 0.f;
    float ns = rsqrtf(fmaxf(dout, 1.f));
    float nd = rsqrtf(fmaxf(di, 1.f));
    g_norm_src[n] = ns;
    g_norm_dst[n] = nd;
    reinterpret_cast<float4*>(g_hA)[n] =
        make_float4(h1 * ns, h2 * ns, h3 * ns, h4 * ns);
    atomicAdd(&g_gcnt[graph_ids[n]], 1.f);
}

__global__ void scatter_kernel(const int* __restrict__ src, const int* __restrict__ dst) {
    int e = blockIdx.x * blockDim.x + threadIdx.x;
    if (e >= EE) return;
    int d = dst[e];
    int pos = atomicAdd(&g_cursor[d], 1);
    g_csr_src[pos] = src[e];
}

// ---------------- layer 1 (4-wide) -------------------------------------------
__global__ void agg1_kernel() {
    int n = blockIdx.x * blockDim.x + threadIdx.x;
    if (n >= NN) return;
    int e0 = g_rowptr[n], e1 = g_rowptr[n + 1];
    const float4* h4 = reinterpret_cast<const float4*>(g_hA);
    float4 acc = make_float4(0.f, 0.f, 0.f, 0.f);
    int e = e0;
    for (; e + 1 < e1; e += 2) {
        float4 v0 = h4[g_csr_src[e]];
        float4 v1 = h4[g_csr_src[e + 1]];
        acc.x += v0.x + v1.x; acc.y += v0.y + v1.y;
        acc.z += v0.z + v1.z; acc.w += v0.w + v1.w;
    }
    if (e < e1) {
        float4 v = h4[g_csr_src[e]];
        acc.x += v.x; acc.y += v.y; acc.z += v.z; acc.w += v.w;
    }
    reinterpret_cast<float4*>(g_agg1)[n] = acc;
}

// writes layer-1 output (pre-scaled by norm_src) into g_hA
__global__ void node_first_kernel(const float* __restrict__ W1, const float* __restrict__ b1) {
    int t = blockIdx.x * blockDim.x + threadIdx.x;
    if (t >= NN * HH) return;
    int n = t >> 6;
    int o = t & 63;
    float nd = g_norm_dst[n];
    float ns = g_norm_src[n];
    float4 x = reinterpret_cast<const float4*>(g_agg1)[n];
    float acc = b1[o];
    acc = fmaf(x.x * nd, W1[0 * HH + o], acc);
    acc = fmaf(x.y * nd, W1[1 * HH + o], acc);
    acc = fmaf(x.z * nd, W1[2 * HH + o], acc);
    acc = fmaf(x.w * nd, W1[3 * HH + o], acc);
    acc = fmaxf(acc, 0.f) * ns;
    g_hA[t] = acc;
}

// ---------------- fused layers 2..4 ------------------------------------------
// One warp = 2 nodes; 16 lanes per node, each lane owns one float4 slice.
// Double-buffered: gather from hin, write hout (no in-place race).
// LAST pools relu(.) into g_gsum instead of writing hout.
template <bool LAST>
__global__ void __launch_bounds__(256) layer_kernel(
        const float* __restrict__ hin, float* __restrict__ hout,
        const float* __restrict__ W, const float* __restrict__ b,
        const int* __restrict__ graph_ids) {
    __shared__ float Ws[HH * HH];
    __shared__ float bs[HH];
    __shared__ float xs[8][2][68];   // [warp][node-in-warp][64+pad]

    int tid = threadIdx.x;
    float4* Ws4 = reinterpret_cast<float4*>(Ws);
    const float4* Wg4 = reinterpret_cast<const float4*>(W);
    for (int i = tid; i < HH * HH / 4; i += 256) Ws4[i] = Wg4[i];
    if (tid < HH) bs[tid] = b[tid];
    __syncthreads();

    int warp = tid >> 5;
    int lane = tid & 31;
    int half = lane >> 4;      // node within warp
    int o4 = lane & 15;        // float4 slice

    const float4* h4 = reinterpret_cast<const float4*>(hin);
    const int* __restrict__ csr = g_csr_src;

    for (int pair = blockIdx.x * 8 + warp; pair * 2 < NN; pair += gridDim.x * 8) {
        int n = pair * 2 + half;
        float4 acc = make_float4(0.f, 0.f, 0.f, 0.f);
        {
            int e0 = g_rowptr[n], e1 = g_rowptr[n + 1];
            int e = e0;
            for (; e + 3 < e1; e += 4) {
                int s0 = csr[e], s1 = csr[e + 1], s2 = csr[e + 2], s3 = csr[e + 3];
                float4 v0 = h4[s0 * 16 + o4];
                float4 v1 = h4[s1 * 16 + o4];
                float4 v2 = h4[s2 * 16 + o4];
                float4 v3 = h4[s3 * 16 + o4];
                acc.x += (v0.x + v1.x) + (v2.x + v3.x);
                acc.y += (v0.y + v1.y) + (v2.y + v3.y);
                acc.z += (v0.z + v1.z) + (v2.z + v3.z);
                acc.w += (v0.w + v1.w) + (v2.w + v3.w);
            }
            for (; e < e1; e++) {
                float4 v = h4[csr[e] * 16 + o4];
                acc.x += v.x; acc.y += v.y; acc.z += v.z; acc.w += v.w;
            }
            float nd = g_norm_dst[n];
            acc.x *= nd; acc.y *= nd; acc.z *= nd; acc.w *= nd;
            reinterpret_cast<float4*>(&xs[warp][half][0])[o4] = acc;
        }
        __syncwarp();
        {
            float4 r = reinterpret_cast<float4*>(bs)[o4];
            const float* xrow = &xs[warp][half][0];
#pragma unroll
            for (int k = 0; k < HH; k++) {
                float xk = xrow[k];
                float4 w = Ws4[k * 16 + o4];
                r.x = fmaf(xk, w.x, r.x);
                r.y = fmaf(xk, w.y, r.y);
                r.z = fmaf(xk, w.z, r.z);
                r.w = fmaf(xk, w.w, r.w);
            }
            r.x = fmaxf(r.x, 0.f);
            r.y = fmaxf(r.y, 0.f);
            r.z = fmaxf(r.z, 0.f);
            r.w = fmaxf(r.w, 0.f);
            if (!LAST) {
                float ns = g_norm_src[n];
                r.x *= ns; r.y *= ns; r.z *= ns; r.w *= ns;
                reinterpret_cast<float4*>(hout)[n * 16 + o4] = r;
            } else {
                int g = graph_ids[n];
                red4(&g_gsum[g * HH + o4 * 4], r);
            }
        }
        __syncwarp();
    }
}

// final head: per-graph mean, dot with Wout, + bout, sigmoid
__global__ void out_kernel(const float* __restrict__ Wout, const float* __restrict__ bout,
                           float* __restrict__ out) {
    __shared__ float s[HH];
    int g = blockIdx.x;
    int t = threadIdx.x;
    float inv = 1.f / g_gcnt[g];
    float v = g_gsum[g * HH + t] * inv * Wout[t];
    s[t] = v;
    __syncthreads();
    if (t < 32) {
        float x = s[t] + s[t + 32];
#pragma unroll
        for (int off = 16; off > 0; off >>= 1)
            x += __shfl_xor_sync(0xFFFFFFFF, x, off);
        if (t == 0) out[g] = 1.f / (1.f + expf(-(x + bout[0])));
    }
}

// ---------------- launch -----------------------------------------------------
extern "C" void kernel_launch(void* const* d_in, const int* in_sizes, int n_in,
                              void* d_out, int out_size) {
    const int*   src  = (const int*)d_in[0];
    const int*   dst  = (const int*)d_in[1];
    const int*   gids = (const int*)d_in[2];
    const float* W1   = (const float*)d_in[3];
    const float* b1   = (const float*)d_in[4];
    const float* W2   = (const float*)d_in[5];
    const float* b2   = (const float*)d_in[6];
    const float* W3   = (const float*)d_in[7];
    const float* b3   = (const float*)d_in[8];
    const float* W4   = (const float*)d_in[9];
    const float* b4   = (const float*)d_in[10];
    const float* Wout = (const float*)d_in[11];
    const float* bout = (const float*)d_in[12];
    float* out = (float*)d_out;

    // device-global buffer addresses for ping-pong
    float *hA, *hB;
    cudaGetSymbolAddress((void**)&hA, g_hA);
    cudaGetSymbolAddress((void**)&hB, g_hB);

    const int T = 256;
    const int gridN  = (NN + T - 1) / T;
    const int gridE  = (EE + T - 1) / T;
    const int gridNH = (NN * HH + T - 1) / T;
    const int gridLayer = 888;   // grid-stride over node pairs

    // CSR build (once; reused for all 4 layers)
    init_kernel<<<gridN, T>>>();
    deg_kernel<<<gridE, T>>>(src, dst);
    scanA_kernel<<<NB, 256>>>();
    scanB_kernel<<<1, 256>>>();
    scanC_feats_kernel<<<gridN, T>>>(gids);
    scatter_kernel<<<gridE, T>>>(src, dst);

    // layer 1 (4-wide): agg from hA[0:4], output (H-wide) back into hA
    agg1_kernel<<<gridN, T>>>();
    node_first_kernel<<<gridNH, T>>>(W1, b1);

    // layers 2..4 fused, double-buffered: A->B, B->A, A->pool
    layer_kernel<false><<<gridLayer, T>>>(hA, hB, W2, b2, gids);
    layer_kernel<false><<<gridLayer, T>>>(hB, hA, W3, b3, gids);
    layer_kernel<true ><<<gridLayer, T>>>(hA, hB, W4, b4, gids);

    out_kernel<<<GG, HH>>>(Wout, bout, out);
}